// round 8
// baseline (speedup 1.0000x reference)
#include <cuda_runtime.h>
#include <cuda_bf16.h>
#include <cstdint>
#include <math.h>

// Problem constants
#define BATCH 4
#define H 1024
#define L 8192
#define KD 64
#define NS 4
#define TAPS 512

// Scratch
__device__ float g_filt[H * TAPS];                     // 2 MB
__device__ float g_v[(size_t)BATCH * H * L];           // 128 MB  v[b,f,l] (tf32-valued)
__device__ float g_w32[H * H];                         // 4 MB    W (tf32-valued)

// ===========================================================================
// Helpers
// ===========================================================================
__device__ __forceinline__ uint32_t f2tf32(float x) {
    uint32_t r;
    asm("cvt.rna.tf32.f32 %0, %1;" : "=r"(r) : "f"(x));
    return r;
}

__device__ __forceinline__ void mma16n8k8(float d[4], const uint32_t a[4],
                                          const uint32_t b[2], const float c[4]) {
    asm volatile(
        "mma.sync.aligned.m16n8k8.row.col.f32.tf32.tf32.f32 "
        "{%0,%1,%2,%3}, {%4,%5,%6,%7}, {%8,%9}, {%10,%11,%12,%13};"
        : "=f"(d[0]), "=f"(d[1]), "=f"(d[2]), "=f"(d[3])
        : "r"(a[0]), "r"(a[1]), "r"(a[2]), "r"(a[3]),
          "r"(b[0]), "r"(b[1]),
          "f"(c[0]), "f"(c[1]), "f"(c[2]), "f"(c[3]));
}

__device__ __forceinline__ uint32_t smem_u32(const void* p) {
    uint32_t a;
    asm("{ .reg .u64 t; cvta.to.shared.u64 t, %1; cvt.u32.u64 %0, t; }" : "=r"(a) : "l"(p));
    return a;
}
__device__ __forceinline__ void cp_async16(uint32_t dst, const void* src) {
    asm volatile("cp.async.cg.shared.global [%0], [%1], 16;" :: "r"(dst), "l"(src));
}

// ===========================================================================
// Kernel 1: build the multi-resolution filter, L2-normalized per head.
// ===========================================================================
__global__ void build_filter_kernel(const float* __restrict__ k0,
                                    const float* __restrict__ k1,
                                    const float* __restrict__ k2,
                                    const float* __restrict__ k3) {
    int h = blockIdx.x;
    int t = threadIdx.x;

    const float* ks[NS] = {k0, k1, k2, k3};
    float acc = 0.0f;
#pragma unroll
    for (int i = 0; i < NS; ++i) {
        int len = KD << i;
        if (t < len) {
            float scale = (float)(1 << i);
            float coord = ((float)t + 0.5f) / scale - 0.5f;
            coord = fminf(fmaxf(coord, 0.0f), (float)(KD - 1));
            int lo = (int)floorf(coord);
            int hi = min(lo + 1, KD - 1);
            float w = coord - (float)lo;
            const float* kp = ks[i] + h * KD;
            float v = kp[lo] * (1.0f - w) + kp[hi] * w;
            acc += v * (float)(1 << (NS - 1 - i));
        }
    }

    __shared__ float red[TAPS];
    red[t] = acc * acc;
    __syncthreads();
#pragma unroll
    for (int s = TAPS / 2; s > 0; s >>= 1) {
        if (t < s) red[t] += red[t + s];
        __syncthreads();
    }
    float inv_norm = rsqrtf(red[0]);
    g_filt[h * TAPS + t] = acc * inv_norm;
}

// ===========================================================================
// Kernel 1b: W -> tf32-valued copy
// ===========================================================================
__global__ void wprep_kernel(const float* __restrict__ Wm) {
    int i = blockIdx.x * 256 + threadIdx.x;
    g_w32[i] = __uint_as_float(f2tf32(Wm[i]));
}

// ===========================================================================
// Kernel 2: Toeplitz-MMA conv: y = k (*) u  + D*u, GeLU -> g_v (tf32-valued)
// ===========================================================================
#define UPAD_ROWS 136
#define UPAD_STRIDE 68

__global__ __launch_bounds__(128)
void conv_mma_kernel(const float* __restrict__ u, const float* __restrict__ D) {
    __shared__ uint32_t u_s[UPAD_ROWS * UPAD_STRIDE];
    __shared__ uint32_t k_s[640];

    int bh = blockIdx.x;
    int h  = bh & (H - 1);
    int tid  = threadIdx.x;
    int lane = tid & 31;
    int wid  = tid >> 5;
    int gid = lane >> 2;
    int tig = lane & 3;

    int wm0 = (wid & 1) * 64;
    int wn0 = (wid >> 1) * 32;

    const float* up = u + (size_t)bh * L;

    for (int i = tid; i < 640; i += 128) {
        int t = i - 64;
        float v = (t >= 0 && t < TAPS) ? g_filt[h * TAPS + t] : 0.0f;
        k_s[i] = f2tf32(v);
    }
    for (int j = tid; j < 512; j += 128)
        u_s[(j >> 6) * UPAD_STRIDE + (j & 63)] = 0u;
    for (int j = tid; j < L / 4; j += 128) {
        float4 x = ((const float4*)up)[j];
        int i = 512 + j * 4;
        uint32_t* p = u_s + (i >> 6) * UPAD_STRIDE + (i & 63);
        p[0] = f2tf32(x.x); p[1] = f2tf32(x.y);
        p[2] = f2tf32(x.z); p[3] = f2tf32(x.w);
    }
    __syncthreads();

    float acc[4][4][4];
#pragma unroll
    for (int s = 0; s < 4; ++s)
#pragma unroll
        for (int q = 0; q < 4; ++q)
#pragma unroll
            for (int e = 0; e < 4; ++e) acc[s][q][e] = 0.0f;

#pragma unroll 1
    for (int d = 0; d < 9; ++d) {
        int arow = (wm0 + gid + 8 - d) * UPAD_STRIDE + tig;
        int bb   = 64 + wn0 + gid - tig + 64 * d;
#pragma unroll
        for (int ms = 0; ms < 64; ms += 8) {
            uint32_t a[4][4];
#pragma unroll
            for (int s = 0; s < 4; ++s) {
                int base = arow + s * (16 * UPAD_STRIDE) + ms;
                a[s][0] = u_s[base];
                a[s][1] = u_s[base + 8 * UPAD_STRIDE];
                a[s][2] = u_s[base + 4];
                a[s][3] = u_s[base + 8 * UPAD_STRIDE + 4];
            }
            uint32_t bf[4][2];
#pragma unroll
            for (int q = 0; q < 4; ++q) {
                int kb = bb - ms + q * 8;
                bf[q][0] = k_s[kb];
                bf[q][1] = k_s[kb - 4];
            }
#pragma unroll
            for (int s = 0; s < 4; ++s)
#pragma unroll
                for (int q = 0; q < 4; ++q)
                    mma16n8k8(acc[s][q], a[s], bf[q], acc[s][q]);
        }
    }

    float dv = D[h];
    float* vp = g_v + (size_t)bh * L;
#pragma unroll
    for (int s = 0; s < 4; ++s) {
        int r0 = wm0 + s * 16 + gid;
#pragma unroll
        for (int q = 0; q < 4; ++q) {
            int n = wn0 + q * 8 + 2 * tig;
#pragma unroll
            for (int half = 0; half < 2; ++half) {
                int r = r0 + half * 8;
                float y0 = acc[s][q][half * 2 + 0];
                float y1 = acc[s][q][half * 2 + 1];
                float u0 = __uint_as_float(u_s[(r + 8) * UPAD_STRIDE + n]);
                float u1 = __uint_as_float(u_s[(r + 8) * UPAD_STRIDE + n + 1]);
                float x0 = y0 + dv * u0;
                float x1 = y1 + dv * u1;
                float g0 = 0.5f * x0 * (1.0f + erff(x0 * 0.70710678118654752f));
                float g1 = 0.5f * x1 * (1.0f + erff(x1 * 0.70710678118654752f));
                *(float2*)(vp + r * 64 + n) =
                    make_float2(__uint_as_float(f2tf32(g0)), __uint_as_float(f2tf32(g1)));
            }
        }
    }
}

// ===========================================================================
// Kernel 3: tf32 mma.sync GEMM, cp.async 3-stage pipeline, 512 threads.
//   out[b,o,l] = sum_f W[o,f] * v[b,f,l] + bias[o]
//   CTA tile 256(M) x 128(N) x 32(K); 16 warps (4M x 4N), warp tile 64x32.
// ===========================================================================
#define GBM 256
#define GBN 128
#define GBK 32
#define GAS 36            // A_s row stride (words)
#define GBS 136           // B_s row stride (words)
#define GSTG 3
#define A_STAGE_W (GBM * GAS)              // 9216 words
#define B_STAGE_W (GBK * GBS)              // 4352 words
#define STAGE_W (A_STAGE_W + B_STAGE_W)    // 13568 words
#define GEMM_SMEM_BYTES (GSTG * STAGE_W * 4)
#define GNCHUNK (H / GBK)                  // 32

extern __shared__ uint32_t g_smem[];

__global__ __launch_bounds__(512, 1)
void gemm_mma_pipe(const float* __restrict__ bias, float* __restrict__ out) {
    int bz = blockIdx.z;
    int nb = blockIdx.x * GBN;
    int mb = blockIdx.y * GBM;
    const float* v = g_v + (size_t)bz * H * L;

    int tid  = threadIdx.x;
    int lane = tid & 31;
    int wid  = tid >> 5;           // 0..15
    int wm0 = (wid & 3) * 64;      // warp M offset
    int wn0 = (wid >> 2) * 32;     // warp N offset
    int gid = lane >> 2;
    int tig = lane & 3;

    uint32_t sbase = smem_u32(g_smem);

    // cp.async mapping: A: 64 rows/rep x 8 slots (4 reps); B: 16 rows/rep x 32 slots (2 reps)
    int a_row = tid >> 3, a_slot = tid & 7;
    int b_row = tid >> 5, b_slot = tid & 31;

    const float* Ag = g_w32 + (size_t)(mb + a_row) * H + a_slot * 4;
    const float* Bg = v + (size_t)b_row * L + nb + b_slot * 4;

    uint32_t a_doff = (uint32_t)(a_row * GAS + a_slot * 4) * 4u;
    uint32_t b_doff = (uint32_t)(b_row * GBS + b_slot * 4) * 4u;

#define ISSUE_CHUNK(c_) do {                                                  \
        int st_ = (c_) % GSTG;                                                \
        uint32_t sa_ = sbase + (uint32_t)(st_ * STAGE_W) * 4u;                \
        uint32_t sb_ = sa_ + (uint32_t)A_STAGE_W * 4u;                        \
        const float* ag_ = Ag + (c_) * GBK;                                   \
        const float* bg_ = Bg + (size_t)(c_) * GBK * L;                       \
        _Pragma("unroll")                                                     \
        for (int r_ = 0; r_ < 4; ++r_)                                        \
            cp_async16(sa_ + a_doff + (uint32_t)(r_ * 64 * GAS) * 4u,         \
                       ag_ + (size_t)(r_ * 64) * H);                          \
        _Pragma("unroll")                                                     \
        for (int r_ = 0; r_ < 2; ++r_)                                        \
            cp_async16(sb_ + b_doff + (uint32_t)(r_ * 16 * GBS) * 4u,         \
                       bg_ + (size_t)(r_ * 16) * L);                          \
    } while (0)

#pragma unroll
    for (int c = 0; c < GSTG - 1; ++c) {
        ISSUE_CHUNK(c);
        asm volatile("cp.async.commit_group;" ::: "memory");
    }

    float acc[4][4][4];
#pragma unroll
    for (int s = 0; s < 4; ++s)
#pragma unroll
        for (int q = 0; q < 4; ++q)
#pragma unroll
            for (int e = 0; e < 4; ++e) acc[s][q][e] = 0.0f;

#pragma unroll 1
    for (int c = 0; c < GNCHUNK; ++c) {
        asm volatile("cp.async.wait_group %0;" :: "n"(GSTG - 2) : "memory");
        __syncthreads();

        if (c + GSTG - 1 < GNCHUNK) ISSUE_CHUNK(c + GSTG - 1);
        asm volatile("cp.async.commit_group;" ::: "memory");

        const uint32_t* As = g_smem + (c % GSTG) * STAGE_W;
        const uint32_t* Bs = As + A_STAGE_W;

#pragma unroll
        for (int kk = 0; kk < GBK; kk += 8) {
            uint32_t a[4][4];
#pragma unroll
            for (int s = 0; s < 4; ++s) {
                int m0 = wm0 + s * 16 + gid;
                a[s][0] = As[m0 * GAS + kk + tig];
                a[s][1] = As[(m0 + 8) * GAS + kk + tig];
                a[s][2] = As[m0 * GAS + kk + tig + 4];
                a[s][3] = As[(m0 + 8) * GAS + kk + tig + 4];
            }
            uint32_t bf[4][2];
#pragma unroll
            for (int q = 0; q < 4; ++q) {
                bf[q][0] = Bs[(kk + tig) * GBS + wn0 + q * 8 + gid];
                bf[q][1] = Bs[(kk + tig + 4) * GBS + wn0 + q * 8 + gid];
            }
#pragma unroll
            for (int s = 0; s < 4; ++s)
#pragma unroll
                for (int q = 0; q < 4; ++q)
                    mma16n8k8(acc[s][q], a[s], bf[q], acc[s][q]);
        }
    }

    // ---- epilogue ----
#pragma unroll
    for (int s = 0; s < 4; ++s) {
        int r0 = mb + wm0 + s * 16 + gid;
        int r1 = r0 + 8;
        float bv0 = bias[r0];
        float bv1 = bias[r1];
        float* o0 = out + ((size_t)bz * H + r0) * L + nb + wn0 + tig * 2;
        float* o1 = out + ((size_t)bz * H + r1) * L + nb + wn0 + tig * 2;
#pragma unroll
        for (int q = 0; q < 4; ++q) {
            *(float2*)(o0 + q * 8) = make_float2(acc[s][q][0] + bv0, acc[s][q][1] + bv0);
            *(float2*)(o1 + q * 8) = make_float2(acc[s][q][2] + bv1, acc[s][q][3] + bv1);
        }
    }
}

// ===========================================================================
// Launch
// ===========================================================================
extern "C" void kernel_launch(void* const* d_in, const int* in_sizes, int n_in,
                              void* d_out, int out_size) {
    const float* u  = (const float*)d_in[0];
    const float* k0 = (const float*)d_in[1];
    const float* k1 = (const float*)d_in[2];
    const float* k2 = (const float*)d_in[3];
    const float* k3 = (const float*)d_in[4];
    const float* D  = (const float*)d_in[5];
    const float* Wm = (const float*)d_in[6];
    const float* b  = (const float*)d_in[7];
    float* out = (float*)d_out;

    build_filter_kernel<<<H, TAPS>>>(k0, k1, k2, k3);
    wprep_kernel<<<H * H / 256, 256>>>(Wm);

    conv_mma_kernel<<<BATCH * H, 128>>>(u, D);

    static bool attr_set = false;
    if (!attr_set) {
        cudaFuncSetAttribute(gemm_mma_pipe,
                             cudaFuncAttributeMaxDynamicSharedMemorySize,
                             GEMM_SMEM_BYTES);
        attr_set = true;
    }
    dim3 ggrid(L / GBN, H / GBM, BATCH);
    gemm_mma_pipe<<<ggrid, 512, GEMM_SMEM_BYTES>>>(b, out);
}

// round 9
// speedup vs baseline: 1.0600x; 1.0600x over previous
#include <cuda_runtime.h>
#include <cuda_bf16.h>
#include <cstdint>
#include <math.h>

// Problem constants
#define BATCH 4
#define H 1024
#define L 8192
#define KD 64
#define NS 4
#define TAPS 512

// Scratch
__device__ float g_filt[H * TAPS];                     // 2 MB
__device__ float g_v[(size_t)BATCH * H * L];           // 128 MB  v[b,f,l] (tf32-valued)
__device__ float g_w32[H * H];                         // 4 MB    W (tf32-valued)

// ===========================================================================
// Helpers
// ===========================================================================
__device__ __forceinline__ uint32_t f2tf32(float x) {
    uint32_t r;
    asm("cvt.rna.tf32.f32 %0, %1;" : "=r"(r) : "f"(x));
    return r;
}

__device__ __forceinline__ void mma16n8k8(float d[4], const uint32_t a[4],
                                          const uint32_t b[2], const float c[4]) {
    asm volatile(
        "mma.sync.aligned.m16n8k8.row.col.f32.tf32.tf32.f32 "
        "{%0,%1,%2,%3}, {%4,%5,%6,%7}, {%8,%9}, {%10,%11,%12,%13};"
        : "=f"(d[0]), "=f"(d[1]), "=f"(d[2]), "=f"(d[3])
        : "r"(a[0]), "r"(a[1]), "r"(a[2]), "r"(a[3]),
          "r"(b[0]), "r"(b[1]),
          "f"(c[0]), "f"(c[1]), "f"(c[2]), "f"(c[3]));
}

__device__ __forceinline__ uint32_t smem_u32(const void* p) {
    uint32_t a;
    asm("{ .reg .u64 t; cvta.to.shared.u64 t, %1; cvt.u32.u64 %0, t; }" : "=r"(a) : "l"(p));
    return a;
}
__device__ __forceinline__ void cp_async16(uint32_t dst, const void* src) {
    asm volatile("cp.async.cg.shared.global [%0], [%1], 16;" :: "r"(dst), "l"(src));
}

// ===========================================================================
// Kernel 1: build the multi-resolution filter, L2-normalized per head.
// ===========================================================================
__global__ void build_filter_kernel(const float* __restrict__ k0,
                                    const float* __restrict__ k1,
                                    const float* __restrict__ k2,
                                    const float* __restrict__ k3) {
    int h = blockIdx.x;
    int t = threadIdx.x;

    const float* ks[NS] = {k0, k1, k2, k3};
    float acc = 0.0f;
#pragma unroll
    for (int i = 0; i < NS; ++i) {
        int len = KD << i;
        if (t < len) {
            float scale = (float)(1 << i);
            float coord = ((float)t + 0.5f) / scale - 0.5f;
            coord = fminf(fmaxf(coord, 0.0f), (float)(KD - 1));
            int lo = (int)floorf(coord);
            int hi = min(lo + 1, KD - 1);
            float w = coord - (float)lo;
            const float* kp = ks[i] + h * KD;
            float v = kp[lo] * (1.0f - w) + kp[hi] * w;
            acc += v * (float)(1 << (NS - 1 - i));
        }
    }

    __shared__ float red[TAPS];
    red[t] = acc * acc;
    __syncthreads();
#pragma unroll
    for (int s = TAPS / 2; s > 0; s >>= 1) {
        if (t < s) red[t] += red[t + s];
        __syncthreads();
    }
    float inv_norm = rsqrtf(red[0]);
    g_filt[h * TAPS + t] = acc * inv_norm;
}

// ===========================================================================
// Kernel 1b: W -> tf32-valued copy
// ===========================================================================
__global__ void wprep_kernel(const float* __restrict__ Wm) {
    int i = blockIdx.x * 256 + threadIdx.x;
    g_w32[i] = __uint_as_float(f2tf32(Wm[i]));
}

// ===========================================================================
// Kernel 2: Toeplitz-MMA conv: y = k (*) u  + D*u, GeLU -> g_v (tf32-valued)
// ===========================================================================
#define UPAD_ROWS 136
#define UPAD_STRIDE 68

__global__ __launch_bounds__(128)
void conv_mma_kernel(const float* __restrict__ u, const float* __restrict__ D) {
    __shared__ uint32_t u_s[UPAD_ROWS * UPAD_STRIDE];
    __shared__ uint32_t k_s[640];

    int bh = blockIdx.x;
    int h  = bh & (H - 1);
    int tid  = threadIdx.x;
    int lane = tid & 31;
    int wid  = tid >> 5;
    int gid = lane >> 2;
    int tig = lane & 3;

    int wm0 = (wid & 1) * 64;
    int wn0 = (wid >> 1) * 32;

    const float* up = u + (size_t)bh * L;

    for (int i = tid; i < 640; i += 128) {
        int t = i - 64;
        float v = (t >= 0 && t < TAPS) ? g_filt[h * TAPS + t] : 0.0f;
        k_s[i] = f2tf32(v);
    }
    for (int j = tid; j < 512; j += 128)
        u_s[(j >> 6) * UPAD_STRIDE + (j & 63)] = 0u;
    for (int j = tid; j < L / 4; j += 128) {
        float4 x = ((const float4*)up)[j];
        int i = 512 + j * 4;
        uint32_t* p = u_s + (i >> 6) * UPAD_STRIDE + (i & 63);
        p[0] = f2tf32(x.x); p[1] = f2tf32(x.y);
        p[2] = f2tf32(x.z); p[3] = f2tf32(x.w);
    }
    __syncthreads();

    float acc[4][4][4];
#pragma unroll
    for (int s = 0; s < 4; ++s)
#pragma unroll
        for (int q = 0; q < 4; ++q)
#pragma unroll
            for (int e = 0; e < 4; ++e) acc[s][q][e] = 0.0f;

#pragma unroll 1
    for (int d = 0; d < 9; ++d) {
        int arow = (wm0 + gid + 8 - d) * UPAD_STRIDE + tig;
        int bb   = 64 + wn0 + gid - tig + 64 * d;
#pragma unroll
        for (int ms = 0; ms < 64; ms += 8) {
            uint32_t a[4][4];
#pragma unroll
            for (int s = 0; s < 4; ++s) {
                int base = arow + s * (16 * UPAD_STRIDE) + ms;
                a[s][0] = u_s[base];
                a[s][1] = u_s[base + 8 * UPAD_STRIDE];
                a[s][2] = u_s[base + 4];
                a[s][3] = u_s[base + 8 * UPAD_STRIDE + 4];
            }
            uint32_t bf[4][2];
#pragma unroll
            for (int q = 0; q < 4; ++q) {
                int kb = bb - ms + q * 8;
                bf[q][0] = k_s[kb];
                bf[q][1] = k_s[kb - 4];
            }
#pragma unroll
            for (int s = 0; s < 4; ++s)
#pragma unroll
                for (int q = 0; q < 4; ++q)
                    mma16n8k8(acc[s][q], a[s], bf[q], acc[s][q]);
        }
    }

    float dv = D[h];
    float* vp = g_v + (size_t)bh * L;
#pragma unroll
    for (int s = 0; s < 4; ++s) {
        int r0 = wm0 + s * 16 + gid;
#pragma unroll
        for (int q = 0; q < 4; ++q) {
            int n = wn0 + q * 8 + 2 * tig;
#pragma unroll
            for (int half = 0; half < 2; ++half) {
                int r = r0 + half * 8;
                float y0 = acc[s][q][half * 2 + 0];
                float y1 = acc[s][q][half * 2 + 1];
                float u0 = __uint_as_float(u_s[(r + 8) * UPAD_STRIDE + n]);
                float u1 = __uint_as_float(u_s[(r + 8) * UPAD_STRIDE + n + 1]);
                float x0 = y0 + dv * u0;
                float x1 = y1 + dv * u1;
                float g0 = 0.5f * x0 * (1.0f + erff(x0 * 0.70710678118654752f));
                float g1 = 0.5f * x1 * (1.0f + erff(x1 * 0.70710678118654752f));
                *(float2*)(vp + r * 64 + n) =
                    make_float2(__uint_as_float(f2tf32(g0)), __uint_as_float(f2tf32(g1)));
            }
        }
    }
}

// ===========================================================================
// Kernel 3: tf32 mma.sync GEMM, cp.async 3-stage pipeline, 2 CTAs/SM.
//   out[b,o,l] = sum_f W[o,f] * v[b,f,l] + bias[o]
//   CTA tile 128(M) x 128(N) x 32(K); 8 warps (4M x 2N), warp tile 32x64.
// ===========================================================================
#define GBM 128
#define GBN 128
#define GBK 32
#define GAS 36            // A_s row stride (words)
#define GBS 136           // B_s row stride (words)
#define GSTG 3
#define A_STAGE_W (GBM * GAS)              // 4608 words
#define B_STAGE_W (GBK * GBS)              // 4352 words
#define STAGE_W (A_STAGE_W + B_STAGE_W)    // 8960 words
#define GEMM_SMEM_BYTES (GSTG * STAGE_W * 4)   // 107520 B
#define GNCHUNK (H / GBK)                  // 32

extern __shared__ uint32_t g_smem[];

__global__ __launch_bounds__(256, 2)
void gemm_mma_pipe(const float* __restrict__ bias, float* __restrict__ out) {
    int bz = blockIdx.z;
    int nb = blockIdx.x * GBN;
    int mb = blockIdx.y * GBM;
    const float* v = g_v + (size_t)bz * H * L;

    int tid  = threadIdx.x;
    int lane = tid & 31;
    int wid  = tid >> 5;           // 0..7
    int wm0 = (wid & 3) * 32;      // warp M offset
    int wn0 = (wid >> 2) * 64;     // warp N offset
    int gid = lane >> 2;
    int tig = lane & 3;

    uint32_t sbase = smem_u32(g_smem);

    // cp.async mapping: A: 32 rows/rep x 8 slots (4 reps); B: 8 rows/rep x 32 slots (4 reps)
    int a_row = tid >> 3, a_slot = tid & 7;
    int b_row = tid >> 5, b_slot = tid & 31;

    const float* Ag = g_w32 + (size_t)(mb + a_row) * H + a_slot * 4;
    const float* Bg = v + (size_t)b_row * L + nb + b_slot * 4;

    uint32_t a_doff = (uint32_t)(a_row * GAS + a_slot * 4) * 4u;
    uint32_t b_doff = (uint32_t)(b_row * GBS + b_slot * 4) * 4u;

#define ISSUE_CHUNK(c_) do {                                                  \
        int st_ = (c_) % GSTG;                                                \
        uint32_t sa_ = sbase + (uint32_t)(st_ * STAGE_W) * 4u;                \
        uint32_t sb_ = sa_ + (uint32_t)A_STAGE_W * 4u;                        \
        const float* ag_ = Ag + (c_) * GBK;                                   \
        const float* bg_ = Bg + (size_t)(c_) * GBK * L;                       \
        _Pragma("unroll")                                                     \
        for (int r_ = 0; r_ < 4; ++r_)                                        \
            cp_async16(sa_ + a_doff + (uint32_t)(r_ * 32 * GAS) * 4u,         \
                       ag_ + (size_t)(r_ * 32) * H);                          \
        _Pragma("unroll")                                                     \
        for (int r_ = 0; r_ < 4; ++r_)                                        \
            cp_async16(sb_ + b_doff + (uint32_t)(r_ * 8 * GBS) * 4u,          \
                       bg_ + (size_t)(r_ * 8) * L);                           \
    } while (0)

#pragma unroll
    for (int c = 0; c < GSTG - 1; ++c) {
        ISSUE_CHUNK(c);
        asm volatile("cp.async.commit_group;" ::: "memory");
    }

    float acc[2][8][4];
#pragma unroll
    for (int s = 0; s < 2; ++s)
#pragma unroll
        for (int j = 0; j < 8; ++j)
#pragma unroll
            for (int e = 0; e < 4; ++e) acc[s][j][e] = 0.0f;

#pragma unroll 1
    for (int c = 0; c < GNCHUNK; ++c) {
        asm volatile("cp.async.wait_group %0;" :: "n"(GSTG - 2) : "memory");
        __syncthreads();

        if (c + GSTG - 1 < GNCHUNK) ISSUE_CHUNK(c + GSTG - 1);
        asm volatile("cp.async.commit_group;" ::: "memory");

        const uint32_t* As = g_smem + (c % GSTG) * STAGE_W;
        const uint32_t* Bs = As + A_STAGE_W;

#pragma unroll
        for (int kk = 0; kk < GBK; kk += 8) {
            uint32_t a[2][4];
#pragma unroll
            for (int s = 0; s < 2; ++s) {
                int m0 = wm0 + s * 16 + gid;
                a[s][0] = As[m0 * GAS + kk + tig];
                a[s][1] = As[(m0 + 8) * GAS + kk + tig];
                a[s][2] = As[m0 * GAS + kk + tig + 4];
                a[s][3] = As[(m0 + 8) * GAS + kk + tig + 4];
            }
            uint32_t bf[8][2];
#pragma unroll
            for (int j = 0; j < 8; ++j) {
                bf[j][0] = Bs[(kk + tig) * GBS + wn0 + j * 8 + gid];
                bf[j][1] = Bs[(kk + tig + 4) * GBS + wn0 + j * 8 + gid];
            }
#pragma unroll
            for (int s = 0; s < 2; ++s)
#pragma unroll
                for (int j = 0; j < 8; ++j)
                    mma16n8k8(acc[s][j], a[s], bf[j], acc[s][j]);
        }
    }

    // ---- epilogue ----
#pragma unroll
    for (int s = 0; s < 2; ++s) {
        int r0 = mb + wm0 + s * 16 + gid;
        int r1 = r0 + 8;
        float bv0 = bias[r0];
        float bv1 = bias[r1];
        float* o0 = out + ((size_t)bz * H + r0) * L + nb + wn0 + tig * 2;
        float* o1 = out + ((size_t)bz * H + r1) * L + nb + wn0 + tig * 2;
#pragma unroll
        for (int j = 0; j < 8; ++j) {
            *(float2*)(o0 + j * 8) = make_float2(acc[s][j][0] + bv0, acc[s][j][1] + bv0);
            *(float2*)(o1 + j * 8) = make_float2(acc[s][j][2] + bv1, acc[s][j][3] + bv1);
        }
    }
}

// ===========================================================================
// Launch
// ===========================================================================
extern "C" void kernel_launch(void* const* d_in, const int* in_sizes, int n_in,
                              void* d_out, int out_size) {
    const float* u  = (const float*)d_in[0];
    const float* k0 = (const float*)d_in[1];
    const float* k1 = (const float*)d_in[2];
    const float* k2 = (const float*)d_in[3];
    const float* k3 = (const float*)d_in[4];
    const float* D  = (const float*)d_in[5];
    const float* Wm = (const float*)d_in[6];
    const float* b  = (const float*)d_in[7];
    float* out = (float*)d_out;

    build_filter_kernel<<<H, TAPS>>>(k0, k1, k2, k3);
    wprep_kernel<<<H * H / 256, 256>>>(Wm);

    conv_mma_kernel<<<BATCH * H, 128>>>(u, D);

    static bool attr_set = false;
    if (!attr_set) {
        cudaFuncSetAttribute(gemm_mma_pipe,
                             cudaFuncAttributeMaxDynamicSharedMemorySize,
                             GEMM_SMEM_BYTES);
        attr_set = true;
    }
    dim3 ggrid(L / GBN, H / GBM, BATCH);
    gemm_mma_pipe<<<ggrid, 256, GEMM_SMEM_BYTES>>>(b, out);
}

// round 10
// speedup vs baseline: 1.3328x; 1.2574x over previous
#include <cuda_runtime.h>
#include <cuda_fp16.h>
#include <cstdint>
#include <math.h>

// Problem constants
#define BATCH 4
#define H 1024
#define L 8192
#define KD 64
#define NS 4
#define TAPS 512

// Scratch
__device__ float g_filt[H * TAPS];                       // 2 MB
__device__ float g_v[(size_t)BATCH * H * L];             // 128 MB  v[b,h,l] fp32
__device__ __half g_vt[(size_t)BATCH * L * H];           // 64 MB   vt[b,l,h] fp16
__device__ __half g_wh[H * H];                           // 2 MB    W fp16

// ===========================================================================
// Helpers
// ===========================================================================
__device__ __forceinline__ uint32_t f2tf32(float x) {
    uint32_t r;
    asm("cvt.rna.tf32.f32 %0, %1;" : "=r"(r) : "f"(x));
    return r;
}

// tf32 k8 mma (conv kernel)
__device__ __forceinline__ void mma16n8k8(float d[4], const uint32_t a[4],
                                          const uint32_t b[2], const float c[4]) {
    asm volatile(
        "mma.sync.aligned.m16n8k8.row.col.f32.tf32.tf32.f32 "
        "{%0,%1,%2,%3}, {%4,%5,%6,%7}, {%8,%9}, {%10,%11,%12,%13};"
        : "=f"(d[0]), "=f"(d[1]), "=f"(d[2]), "=f"(d[3])
        : "r"(a[0]), "r"(a[1]), "r"(a[2]), "r"(a[3]),
          "r"(b[0]), "r"(b[1]),
          "f"(c[0]), "f"(c[1]), "f"(c[2]), "f"(c[3]));
}

// fp16 k16 mma (GEMM)
__device__ __forceinline__ void mma16n8k16h(float d[4], const uint32_t a[4],
                                            const uint32_t b[2], const float c[4]) {
    asm volatile(
        "mma.sync.aligned.m16n8k16.row.col.f32.f16.f16.f32 "
        "{%0,%1,%2,%3}, {%4,%5,%6,%7}, {%8,%9}, {%10,%11,%12,%13};"
        : "=f"(d[0]), "=f"(d[1]), "=f"(d[2]), "=f"(d[3])
        : "r"(a[0]), "r"(a[1]), "r"(a[2]), "r"(a[3]),
          "r"(b[0]), "r"(b[1]),
          "f"(c[0]), "f"(c[1]), "f"(c[2]), "f"(c[3]));
}

__device__ __forceinline__ uint32_t smem_u32(const void* p) {
    uint32_t a;
    asm("{ .reg .u64 t; cvta.to.shared.u64 t, %1; cvt.u32.u64 %0, t; }" : "=r"(a) : "l"(p));
    return a;
}
__device__ __forceinline__ void cp_async16(uint32_t dst, const void* src) {
    asm volatile("cp.async.cg.shared.global [%0], [%1], 16;" :: "r"(dst), "l"(src));
}

// ===========================================================================
// Kernel 1: build the multi-resolution filter, L2-normalized per head.
// ===========================================================================
__global__ void build_filter_kernel(const float* __restrict__ k0,
                                    const float* __restrict__ k1,
                                    const float* __restrict__ k2,
                                    const float* __restrict__ k3) {
    int h = blockIdx.x;
    int t = threadIdx.x;

    const float* ks[NS] = {k0, k1, k2, k3};
    float acc = 0.0f;
#pragma unroll
    for (int i = 0; i < NS; ++i) {
        int len = KD << i;
        if (t < len) {
            float scale = (float)(1 << i);
            float coord = ((float)t + 0.5f) / scale - 0.5f;
            coord = fminf(fmaxf(coord, 0.0f), (float)(KD - 1));
            int lo = (int)floorf(coord);
            int hi = min(lo + 1, KD - 1);
            float w = coord - (float)lo;
            const float* kp = ks[i] + h * KD;
            float v = kp[lo] * (1.0f - w) + kp[hi] * w;
            acc += v * (float)(1 << (NS - 1 - i));
        }
    }

    __shared__ float red[TAPS];
    red[t] = acc * acc;
    __syncthreads();
#pragma unroll
    for (int s = TAPS / 2; s > 0; s >>= 1) {
        if (t < s) red[t] += red[t + s];
        __syncthreads();
    }
    float inv_norm = rsqrtf(red[0]);
    g_filt[h * TAPS + t] = acc * inv_norm;
}

// ===========================================================================
// Kernel 1b: W -> fp16 copy
// ===========================================================================
__global__ void wprep_kernel(const float* __restrict__ Wm) {
    int i = blockIdx.x * 256 + threadIdx.x;
    g_wh[i] = __float2half_rn(Wm[i]);
}

// ===========================================================================
// Kernel 2: Toeplitz-MMA conv: y = k (*) u  + D*u, GeLU -> g_v (fp32)
// ===========================================================================
#define UPAD_ROWS 136
#define UPAD_STRIDE 68

__global__ __launch_bounds__(128)
void conv_mma_kernel(const float* __restrict__ u, const float* __restrict__ D) {
    __shared__ uint32_t u_s[UPAD_ROWS * UPAD_STRIDE];
    __shared__ uint32_t k_s[640];

    int bh = blockIdx.x;
    int h  = bh & (H - 1);
    int tid  = threadIdx.x;
    int lane = tid & 31;
    int wid  = tid >> 5;
    int gid = lane >> 2;
    int tig = lane & 3;

    int wm0 = (wid & 1) * 64;
    int wn0 = (wid >> 1) * 32;

    const float* up = u + (size_t)bh * L;

    for (int i = tid; i < 640; i += 128) {
        int t = i - 64;
        float v = (t >= 0 && t < TAPS) ? g_filt[h * TAPS + t] : 0.0f;
        k_s[i] = f2tf32(v);
    }
    for (int j = tid; j < 512; j += 128)
        u_s[(j >> 6) * UPAD_STRIDE + (j & 63)] = 0u;
    for (int j = tid; j < L / 4; j += 128) {
        float4 x = ((const float4*)up)[j];
        int i = 512 + j * 4;
        uint32_t* p = u_s + (i >> 6) * UPAD_STRIDE + (i & 63);
        p[0] = f2tf32(x.x); p[1] = f2tf32(x.y);
        p[2] = f2tf32(x.z); p[3] = f2tf32(x.w);
    }
    __syncthreads();

    float acc[4][4][4];
#pragma unroll
    for (int s = 0; s < 4; ++s)
#pragma unroll
        for (int q = 0; q < 4; ++q)
#pragma unroll
            for (int e = 0; e < 4; ++e) acc[s][q][e] = 0.0f;

#pragma unroll 1
    for (int d = 0; d < 9; ++d) {
        int arow = (wm0 + gid + 8 - d) * UPAD_STRIDE + tig;
        int bb   = 64 + wn0 + gid - tig + 64 * d;
#pragma unroll
        for (int ms = 0; ms < 64; ms += 8) {
            uint32_t a[4][4];
#pragma unroll
            for (int s = 0; s < 4; ++s) {
                int base = arow + s * (16 * UPAD_STRIDE) + ms;
                a[s][0] = u_s[base];
                a[s][1] = u_s[base + 8 * UPAD_STRIDE];
                a[s][2] = u_s[base + 4];
                a[s][3] = u_s[base + 8 * UPAD_STRIDE + 4];
            }
            uint32_t bf[4][2];
#pragma unroll
            for (int q = 0; q < 4; ++q) {
                int kb = bb - ms + q * 8;
                bf[q][0] = k_s[kb];
                bf[q][1] = k_s[kb - 4];
            }
#pragma unroll
            for (int s = 0; s < 4; ++s)
#pragma unroll
                for (int q = 0; q < 4; ++q)
                    mma16n8k8(acc[s][q], a[s], bf[q], acc[s][q]);
        }
    }

    float dv = D[h];
    float* vp = g_v + (size_t)bh * L;
#pragma unroll
    for (int s = 0; s < 4; ++s) {
        int r0 = wm0 + s * 16 + gid;
#pragma unroll
        for (int q = 0; q < 4; ++q) {
            int n = wn0 + q * 8 + 2 * tig;
#pragma unroll
            for (int half = 0; half < 2; ++half) {
                int r = r0 + half * 8;
                float y0 = acc[s][q][half * 2 + 0];
                float y1 = acc[s][q][half * 2 + 1];
                float u0 = __uint_as_float(u_s[(r + 8) * UPAD_STRIDE + n]);
                float u1 = __uint_as_float(u_s[(r + 8) * UPAD_STRIDE + n + 1]);
                float x0 = y0 + dv * u0;
                float x1 = y1 + dv * u1;
                float g0 = 0.5f * x0 * (1.0f + erff(x0 * 0.70710678118654752f));
                float g1 = 0.5f * x1 * (1.0f + erff(x1 * 0.70710678118654752f));
                *(float2*)(vp + r * 64 + n) = make_float2(g0, g1);
            }
        }
    }
}

// ===========================================================================
// Kernel 2b: transpose+convert  v[b,h,l] fp32 -> vt[b,l,h] fp16
//   64x64 tiles, block 256.
// ===========================================================================
__global__ __launch_bounds__(256)
void transpose_h_kernel() {
    __shared__ float tl[64][65];
    int l0 = blockIdx.x * 64;
    int h0 = blockIdx.y * 64;
    int b  = blockIdx.z;
    int tid = threadIdx.x;

#pragma unroll
    for (int i = 0; i < 16; ++i) {
        int idx = tid + i * 256;
        int r = idx >> 6, c = idx & 63;        // r: h-row, c: l-col
        tl[r][c] = g_v[((size_t)b * H + h0 + r) * L + l0 + c];
    }
    __syncthreads();

    int tx = tid & 31, ty = tid >> 5;
#pragma unroll
    for (int i = 0; i < 8; ++i) {
        int l = ty + i * 8;
        __half2 hv = __floats2half2_rn(tl[2 * tx][l], tl[2 * tx + 1][l]);
        *(__half2*)(g_vt + ((size_t)b * L + l0 + l) * H + h0 + 2 * tx) = hv;
    }
}

// ===========================================================================
// Kernel 3: fp16 mma.sync GEMM (f32 accum), cp.async 3-stage, 2 CTAs/SM.
//   out[b,o,l] = sum_f W[o,f] * vt[b,l,f] + bias[o]
//   CTA tile 128(M=o) x 128(N=l) x 32(K=f); 8 warps (4M x 2N), warp 32x64.
//   Both A and B stored K-major: row stride 20 words (16 data + 4 pad).
// ===========================================================================
#define GBM 128
#define GBN 128
#define GBK 32
#define HRS 20                              // smem row stride, words
#define A_STAGE_W (GBM * HRS)               // 2560 words
#define B_STAGE_W (GBN * HRS)               // 2560 words
#define STAGE_W (A_STAGE_W + B_STAGE_W)     // 5120 words
#define GSTG 3
#define GEMM_SMEM_BYTES (GSTG * STAGE_W * 4)   // 61440 B
#define GNCHUNK (H / GBK)                   // 32

extern __shared__ uint32_t g_smem[];

__global__ __launch_bounds__(256, 2)
void gemm_mma_fp16(const float* __restrict__ bias, float* __restrict__ out) {
    int bz = blockIdx.z;
    int nb = blockIdx.x * GBN;
    int mb = blockIdx.y * GBM;
    const __half* vt = g_vt + (size_t)bz * L * H;

    int tid  = threadIdx.x;
    int lane = tid & 31;
    int wid  = tid >> 5;           // 0..7
    int wm0 = (wid & 3) * 32;      // warp M offset
    int wn0 = (wid >> 2) * 64;     // warp N offset
    int gid = lane >> 2;
    int tig = lane & 3;

    uint32_t sbase = smem_u32(g_smem);

    // cp.async: 64 B per row -> 4 threads/row; 64 rows/pass, 2 passes each op.
    int rrow = tid >> 2, rslot = tid & 3;
    const __half* Ag = g_wh + (size_t)(mb + rrow) * H + rslot * 8;
    const __half* Bg = vt + (size_t)(nb + rrow) * H + rslot * 8;
    uint32_t doff = (uint32_t)(rrow * HRS + rslot * 4) * 4u;

#define ISSUE_CHUNK(c_) do {                                                  \
        int st_ = (c_) % GSTG;                                                \
        uint32_t sa_ = sbase + (uint32_t)(st_ * STAGE_W) * 4u;                \
        uint32_t sb_ = sa_ + (uint32_t)A_STAGE_W * 4u;                        \
        const __half* ag_ = Ag + (c_) * GBK;                                  \
        const __half* bg_ = Bg + (c_) * GBK;                                  \
        _Pragma("unroll")                                                     \
        for (int r_ = 0; r_ < 2; ++r_) {                                      \
            cp_async16(sa_ + doff + (uint32_t)(r_ * 64 * HRS) * 4u,           \
                       ag_ + (size_t)(r_ * 64) * H);                          \
            cp_async16(sb_ + doff + (uint32_t)(r_ * 64 * HRS) * 4u,           \
                       bg_ + (size_t)(r_ * 64) * H);                          \
        }                                                                     \
    } while (0)

#pragma unroll
    for (int c = 0; c < GSTG - 1; ++c) {
        ISSUE_CHUNK(c);
        asm volatile("cp.async.commit_group;" ::: "memory");
    }

    float acc[2][8][4];
#pragma unroll
    for (int s = 0; s < 2; ++s)
#pragma unroll
        for (int j = 0; j < 8; ++j)
#pragma unroll
            for (int e = 0; e < 4; ++e) acc[s][j][e] = 0.0f;

#pragma unroll 1
    for (int c = 0; c < GNCHUNK; ++c) {
        asm volatile("cp.async.wait_group %0;" :: "n"(GSTG - 2) : "memory");
        __syncthreads();

        if (c + GSTG - 1 < GNCHUNK) ISSUE_CHUNK(c + GSTG - 1);
        asm volatile("cp.async.commit_group;" ::: "memory");

        const uint32_t* As = g_smem + (c % GSTG) * STAGE_W;
        const uint32_t* Bs = As + A_STAGE_W;

#pragma unroll
        for (int ks = 0; ks < 2; ++ks) {       // two k16 steps per BK=32
            int kk2 = ks * 8;                  // word offset within row
            uint32_t a[2][4];
#pragma unroll
            for (int s = 0; s < 2; ++s) {
                int m0 = wm0 + s * 16 + gid;
                a[s][0] = As[m0 * HRS + kk2 + tig];
                a[s][1] = As[(m0 + 8) * HRS + kk2 + tig];
                a[s][2] = As[m0 * HRS + kk2 + tig + 4];
                a[s][3] = As[(m0 + 8) * HRS + kk2 + tig + 4];
            }
            uint32_t bf[8][2];
#pragma unroll
            for (int j = 0; j < 8; ++j) {
                int n0 = wn0 + j * 8 + gid;
                bf[j][0] = Bs[n0 * HRS + kk2 + tig];
                bf[j][1] = Bs[n0 * HRS + kk2 + tig + 4];
            }
#pragma unroll
            for (int s = 0; s < 2; ++s)
#pragma unroll
                for (int j = 0; j < 8; ++j)
                    mma16n8k16h(acc[s][j], a[s], bf[j], acc[s][j]);
        }
    }

    // ---- epilogue ----
#pragma unroll
    for (int s = 0; s < 2; ++s) {
        int r0 = mb + wm0 + s * 16 + gid;
        int r1 = r0 + 8;
        float bv0 = bias[r0];
        float bv1 = bias[r1];
        float* o0 = out + ((size_t)bz * H + r0) * L + nb + wn0 + tig * 2;
        float* o1 = out + ((size_t)bz * H + r1) * L + nb + wn0 + tig * 2;
#pragma unroll
        for (int j = 0; j < 8; ++j) {
            *(float2*)(o0 + j * 8) = make_float2(acc[s][j][0] + bv0, acc[s][j][1] + bv0);
            *(float2*)(o1 + j * 8) = make_float2(acc[s][j][2] + bv1, acc[s][j][3] + bv1);
        }
    }
}

// ===========================================================================
// Launch
// ===========================================================================
extern "C" void kernel_launch(void* const* d_in, const int* in_sizes, int n_in,
                              void* d_out, int out_size) {
    const float* u  = (const float*)d_in[0];
    const float* k0 = (const float*)d_in[1];
    const float* k1 = (const float*)d_in[2];
    const float* k2 = (const float*)d_in[3];
    const float* k3 = (const float*)d_in[4];
    const float* D  = (const float*)d_in[5];
    const float* Wm = (const float*)d_in[6];
    const float* b  = (const float*)d_in[7];
    float* out = (float*)d_out;

    build_filter_kernel<<<H, TAPS>>>(k0, k1, k2, k3);
    wprep_kernel<<<H * H / 256, 256>>>(Wm);

    conv_mma_kernel<<<BATCH * H, 128>>>(u, D);

    dim3 tgrid(L / 64, H / 64, BATCH);
    transpose_h_kernel<<<tgrid, 256>>>();

    static bool attr_set = false;
    if (!attr_set) {
        cudaFuncSetAttribute(gemm_mma_fp16,
                             cudaFuncAttributeMaxDynamicSharedMemorySize,
                             GEMM_SMEM_BYTES);
        attr_set = true;
    }
    dim3 ggrid(L / GBN, H / GBM, BATCH);
    gemm_mma_fp16<<<ggrid, 256, GEMM_SMEM_BYTES>>>(b, out);
}

// round 11
// speedup vs baseline: 1.3448x; 1.0090x over previous
#include <cuda_runtime.h>
#include <cuda_fp16.h>
#include <cstdint>
#include <math.h>

// Problem constants
#define BATCH 4
#define H 1024
#define L 8192
#define KD 64
#define NS 4
#define TAPS 512

// Scratch
__device__ float  g_filt[H * TAPS];                      // 2 MB
__device__ __half g_vh[(size_t)BATCH * H * L];           // 64 MB   v[b,h,l] fp16
__device__ __half g_vt[(size_t)BATCH * L * H];           // 64 MB   vt[b,l,h] fp16
__device__ __half g_wh[H * H];                           // 2 MB    W fp16

// ===========================================================================
// Helpers
// ===========================================================================
__device__ __forceinline__ uint32_t f2tf32(float x) {
    uint32_t r;
    asm("cvt.rna.tf32.f32 %0, %1;" : "=r"(r) : "f"(x));
    return r;
}

// tf32 k8 mma (conv kernel)
__device__ __forceinline__ void mma16n8k8(float d[4], const uint32_t a[4],
                                          const uint32_t b[2], const float c[4]) {
    asm volatile(
        "mma.sync.aligned.m16n8k8.row.col.f32.tf32.tf32.f32 "
        "{%0,%1,%2,%3}, {%4,%5,%6,%7}, {%8,%9}, {%10,%11,%12,%13};"
        : "=f"(d[0]), "=f"(d[1]), "=f"(d[2]), "=f"(d[3])
        : "r"(a[0]), "r"(a[1]), "r"(a[2]), "r"(a[3]),
          "r"(b[0]), "r"(b[1]),
          "f"(c[0]), "f"(c[1]), "f"(c[2]), "f"(c[3]));
}

// fp16 k16 mma (GEMM)
__device__ __forceinline__ void mma16n8k16h(float d[4], const uint32_t a[4],
                                            const uint32_t b0, const uint32_t b1,
                                            const float c[4]) {
    asm volatile(
        "mma.sync.aligned.m16n8k16.row.col.f32.f16.f16.f32 "
        "{%0,%1,%2,%3}, {%4,%5,%6,%7}, {%8,%9}, {%10,%11,%12,%13};"
        : "=f"(d[0]), "=f"(d[1]), "=f"(d[2]), "=f"(d[3])
        : "r"(a[0]), "r"(a[1]), "r"(a[2]), "r"(a[3]),
          "r"(b0), "r"(b1),
          "f"(c[0]), "f"(c[1]), "f"(c[2]), "f"(c[3]));
}

__device__ __forceinline__ void ldsm_x4(uint32_t& r0, uint32_t& r1,
                                        uint32_t& r2, uint32_t& r3, uint32_t addr) {
    asm volatile("ldmatrix.sync.aligned.m8n8.x4.shared.b16 {%0,%1,%2,%3}, [%4];"
                 : "=r"(r0), "=r"(r1), "=r"(r2), "=r"(r3) : "r"(addr));
}

__device__ __forceinline__ uint32_t smem_u32(const void* p) {
    uint32_t a;
    asm("{ .reg .u64 t; cvta.to.shared.u64 t, %1; cvt.u32.u64 %0, t; }" : "=r"(a) : "l"(p));
    return a;
}
__device__ __forceinline__ void cp_async16(uint32_t dst, const void* src) {
    asm volatile("cp.async.cg.shared.global [%0], [%1], 16;" :: "r"(dst), "l"(src));
}

// ===========================================================================
// Kernel 1: build the multi-resolution filter, L2-normalized per head.
// ===========================================================================
__global__ void build_filter_kernel(const float* __restrict__ k0,
                                    const float* __restrict__ k1,
                                    const float* __restrict__ k2,
                                    const float* __restrict__ k3) {
    int h = blockIdx.x;
    int t = threadIdx.x;

    const float* ks[NS] = {k0, k1, k2, k3};
    float acc = 0.0f;
#pragma unroll
    for (int i = 0; i < NS; ++i) {
        int len = KD << i;
        if (t < len) {
            float scale = (float)(1 << i);
            float coord = ((float)t + 0.5f) / scale - 0.5f;
            coord = fminf(fmaxf(coord, 0.0f), (float)(KD - 1));
            int lo = (int)floorf(coord);
            int hi = min(lo + 1, KD - 1);
            float w = coord - (float)lo;
            const float* kp = ks[i] + h * KD;
            float v = kp[lo] * (1.0f - w) + kp[hi] * w;
            acc += v * (float)(1 << (NS - 1 - i));
        }
    }

    __shared__ float red[TAPS];
    red[t] = acc * acc;
    __syncthreads();
#pragma unroll
    for (int s = TAPS / 2; s > 0; s >>= 1) {
        if (t < s) red[t] += red[t + s];
        __syncthreads();
    }
    float inv_norm = rsqrtf(red[0]);
    g_filt[h * TAPS + t] = acc * inv_norm;
}

// ===========================================================================
// Kernel 1b: W -> fp16 copy
// ===========================================================================
__global__ void wprep_kernel(const float* __restrict__ Wm) {
    int i = blockIdx.x * 256 + threadIdx.x;
    g_wh[i] = __float2half_rn(Wm[i]);
}

// ===========================================================================
// Kernel 2: Toeplitz-MMA conv: y = k (*) u  + D*u, GeLU -> g_vh (fp16)
// ===========================================================================
#define UPAD_ROWS 136
#define UPAD_STRIDE 68

__global__ __launch_bounds__(128)
void conv_mma_kernel(const float* __restrict__ u, const float* __restrict__ D) {
    __shared__ uint32_t u_s[UPAD_ROWS * UPAD_STRIDE];
    __shared__ uint32_t k_s[640];

    int bh = blockIdx.x;
    int h  = bh & (H - 1);
    int tid  = threadIdx.x;
    int lane = tid & 31;
    int wid  = tid >> 5;
    int gid = lane >> 2;
    int tig = lane & 3;

    int wm0 = (wid & 1) * 64;
    int wn0 = (wid >> 1) * 32;

    const float* up = u + (size_t)bh * L;

    for (int i = tid; i < 640; i += 128) {
        int t = i - 64;
        float v = (t >= 0 && t < TAPS) ? g_filt[h * TAPS + t] : 0.0f;
        k_s[i] = f2tf32(v);
    }
    for (int j = tid; j < 512; j += 128)
        u_s[(j >> 6) * UPAD_STRIDE + (j & 63)] = 0u;
    for (int j = tid; j < L / 4; j += 128) {
        float4 x = ((const float4*)up)[j];
        int i = 512 + j * 4;
        uint32_t* p = u_s + (i >> 6) * UPAD_STRIDE + (i & 63);
        p[0] = f2tf32(x.x); p[1] = f2tf32(x.y);
        p[2] = f2tf32(x.z); p[3] = f2tf32(x.w);
    }
    __syncthreads();

    float acc[4][4][4];
#pragma unroll
    for (int s = 0; s < 4; ++s)
#pragma unroll
        for (int q = 0; q < 4; ++q)
#pragma unroll
            for (int e = 0; e < 4; ++e) acc[s][q][e] = 0.0f;

#pragma unroll 1
    for (int d = 0; d < 9; ++d) {
        int arow = (wm0 + gid + 8 - d) * UPAD_STRIDE + tig;
        int bb   = 64 + wn0 + gid - tig + 64 * d;
#pragma unroll
        for (int ms = 0; ms < 64; ms += 8) {
            uint32_t a[4][4];
#pragma unroll
            for (int s = 0; s < 4; ++s) {
                int base = arow + s * (16 * UPAD_STRIDE) + ms;
                a[s][0] = u_s[base];
                a[s][1] = u_s[base + 8 * UPAD_STRIDE];
                a[s][2] = u_s[base + 4];
                a[s][3] = u_s[base + 8 * UPAD_STRIDE + 4];
            }
            uint32_t bf[4][2];
#pragma unroll
            for (int q = 0; q < 4; ++q) {
                int kb = bb - ms + q * 8;
                bf[q][0] = k_s[kb];
                bf[q][1] = k_s[kb - 4];
            }
#pragma unroll
            for (int s = 0; s < 4; ++s)
#pragma unroll
                for (int q = 0; q < 4; ++q)
                    mma16n8k8(acc[s][q], a[s], bf[q], acc[s][q]);
        }
    }

    float dv = D[h];
    __half* vp = g_vh + (size_t)bh * L;
#pragma unroll
    for (int s = 0; s < 4; ++s) {
        int r0 = wm0 + s * 16 + gid;
#pragma unroll
        for (int q = 0; q < 4; ++q) {
            int n = wn0 + q * 8 + 2 * tig;
#pragma unroll
            for (int half = 0; half < 2; ++half) {
                int r = r0 + half * 8;
                float y0 = acc[s][q][half * 2 + 0];
                float y1 = acc[s][q][half * 2 + 1];
                float u0 = __uint_as_float(u_s[(r + 8) * UPAD_STRIDE + n]);
                float u1 = __uint_as_float(u_s[(r + 8) * UPAD_STRIDE + n + 1]);
                float x0 = y0 + dv * u0;
                float x1 = y1 + dv * u1;
                float g0 = 0.5f * x0 * (1.0f + erff(x0 * 0.70710678118654752f));
                float g1 = 0.5f * x1 * (1.0f + erff(x1 * 0.70710678118654752f));
                *(__half2*)(vp + r * 64 + n) = __floats2half2_rn(g0, g1);
            }
        }
    }
}

// ===========================================================================
// Kernel 2b: transpose  g_vh[b,h,l] fp16 -> vt[b,l,h] fp16, 64x64 tiles.
// ===========================================================================
__global__ __launch_bounds__(256)
void transpose_h_kernel() {
    __shared__ float tl[64][65];
    int l0 = blockIdx.x * 64;
    int h0 = blockIdx.y * 64;
    int b  = blockIdx.z;
    int tid = threadIdx.x;

#pragma unroll
    for (int i = 0; i < 16; ++i) {
        int idx = tid + i * 256;
        int r = idx >> 6, c = idx & 63;        // r: h-row, c: l-col
        tl[r][c] = __half2float(g_vh[((size_t)b * H + h0 + r) * L + l0 + c]);
    }
    __syncthreads();

    int tx = tid & 31, ty = tid >> 5;
#pragma unroll
    for (int i = 0; i < 8; ++i) {
        int l = ty + i * 8;
        __half2 hv = __floats2half2_rn(tl[2 * tx][l], tl[2 * tx + 1][l]);
        *(__half2*)(g_vt + ((size_t)b * L + l0 + l) * H + h0 + 2 * tx) = hv;
    }
}

// ===========================================================================
// Kernel 3: fp16 mma GEMM with ldmatrix.x4, cp.async 3-stage, 2 CTAs/SM.
//   out[b,o,l] = sum_f W[o,f] * vt[b,l,f] + bias[o]
//   CTA tile 128(M=o) x 128(N=l) x 32(K=f); 8 warps (4M x 2N), warp 32x64.
//   A and B K-major rows: 32 fp16 (64B) + 16B pad = 80B (20 words) stride.
// ===========================================================================
#define GBM 128
#define GBN 128
#define GBK 32
#define HRS 20                              // smem row stride, words
#define A_STAGE_W (GBM * HRS)               // 2560 words
#define B_STAGE_W (GBN * HRS)               // 2560 words
#define STAGE_W (A_STAGE_W + B_STAGE_W)     // 5120 words
#define GSTG 3
#define GEMM_SMEM_BYTES (GSTG * STAGE_W * 4)   // 61440 B
#define GNCHUNK (H / GBK)                   // 32

extern __shared__ uint32_t g_smem[];

__global__ __launch_bounds__(256, 2)
void gemm_mma_fp16(const float* __restrict__ bias, float* __restrict__ out) {
    int bz = blockIdx.z;
    int nb = blockIdx.x * GBN;
    int mb = blockIdx.y * GBM;
    const __half* vt = g_vt + (size_t)bz * L * H;

    int tid  = threadIdx.x;
    int lane = tid & 31;
    int wid  = tid >> 5;           // 0..7
    int wm0 = (wid & 3) * 32;      // warp M offset
    int wn0 = (wid >> 2) * 64;     // warp N offset
    int gid = lane >> 2;
    int tig = lane & 3;

    uint32_t sbase = smem_u32(g_smem);

    // cp.async fill mapping
    int rrow = tid >> 2, rslot = tid & 3;
    const __half* Ag = g_wh + (size_t)(mb + rrow) * H + rslot * 8;
    const __half* Bg = vt + (size_t)(nb + rrow) * H + rslot * 8;
    uint32_t doff = (uint32_t)(rrow * HRS + rslot * 4) * 4u;

    // ldmatrix per-lane offsets (bytes within stage)
    int l16 = lane & 15, lhi = lane >> 4;
    uint32_t a_off0 = (uint32_t)((wm0 + l16) * 80 + lhi * 16);
    uint32_t a_off1 = a_off0 + 16 * 80;
    uint32_t b_off[4];
#pragma unroll
    for (int jj = 0; jj < 4; ++jj)
        b_off[jj] = (uint32_t)((wn0 + jj * 16 + l16) * 80 + lhi * 16);

#define ISSUE_CHUNK(c_) do {                                                  \
        int st_ = (c_) % GSTG;                                                \
        uint32_t sa_ = sbase + (uint32_t)(st_ * STAGE_W) * 4u;                \
        uint32_t sb_ = sa_ + (uint32_t)A_STAGE_W * 4u;                        \
        const __half* ag_ = Ag + (c_) * GBK;                                  \
        const __half* bg_ = Bg + (c_) * GBK;                                  \
        _Pragma("unroll")                                                     \
        for (int r_ = 0; r_ < 2; ++r_) {                                      \
            cp_async16(sa_ + doff + (uint32_t)(r_ * 64 * HRS) * 4u,           \
                       ag_ + (size_t)(r_ * 64) * H);                          \
            cp_async16(sb_ + doff + (uint32_t)(r_ * 64 * HRS) * 4u,           \
                       bg_ + (size_t)(r_ * 64) * H);                          \
        }                                                                     \
    } while (0)

#pragma unroll
    for (int c = 0; c < GSTG - 1; ++c) {
        ISSUE_CHUNK(c);
        asm volatile("cp.async.commit_group;" ::: "memory");
    }

    float acc[2][8][4];
#pragma unroll
    for (int s = 0; s < 2; ++s)
#pragma unroll
        for (int j = 0; j < 8; ++j)
#pragma unroll
            for (int e = 0; e < 4; ++e) acc[s][j][e] = 0.0f;

#pragma unroll 1
    for (int c = 0; c < GNCHUNK; ++c) {
        asm volatile("cp.async.wait_group %0;" :: "n"(GSTG - 2) : "memory");
        __syncthreads();

        if (c + GSTG - 1 < GNCHUNK) ISSUE_CHUNK(c + GSTG - 1);
        asm volatile("cp.async.commit_group;" ::: "memory");

        uint32_t sa = sbase + (uint32_t)((c % GSTG) * STAGE_W) * 4u;
        uint32_t sb = sa + (uint32_t)A_STAGE_W * 4u;

#pragma unroll
        for (int ks = 0; ks < 2; ++ks) {       // two k16 steps per BK=32
            uint32_t kof = (uint32_t)(ks * 32);
            uint32_t a[2][4];
            ldsm_x4(a[0][0], a[0][1], a[0][2], a[0][3], sa + a_off0 + kof);
            ldsm_x4(a[1][0], a[1][1], a[1][2], a[1][3], sa + a_off1 + kof);
            uint32_t b0[8], b1[8];
#pragma unroll
            for (int jj = 0; jj < 4; ++jj) {
                uint32_t t0, t1, t2, t3;
                ldsm_x4(t0, t1, t2, t3, sb + b_off[jj] + kof);
                b0[jj * 2]     = t0; b1[jj * 2]     = t2;
                b0[jj * 2 + 1] = t1; b1[jj * 2 + 1] = t3;
            }
#pragma unroll
            for (int s = 0; s < 2; ++s)
#pragma unroll
                for (int j = 0; j < 8; ++j)
                    mma16n8k16h(acc[s][j], a[s], b0[j], b1[j], acc[s][j]);
        }
    }

    // ---- epilogue ----
#pragma unroll
    for (int s = 0; s < 2; ++s) {
        int r0 = mb + wm0 + s * 16 + gid;
        int r1 = r0 + 8;
        float bv0 = bias[r0];
        float bv1 = bias[r1];
        float* o0 = out + ((size_t)bz * H + r0) * L + nb + wn0 + tig * 2;
        float* o1 = out + ((size_t)bz * H + r1) * L + nb + wn0 + tig * 2;
#pragma unroll
        for (int j = 0; j < 8; ++j) {
            *(float2*)(o0 + j * 8) = make_float2(acc[s][j][0] + bv0, acc[s][j][1] + bv0);
            *(float2*)(o1 + j * 8) = make_float2(acc[s][j][2] + bv1, acc[s][j][3] + bv1);
        }
    }
}

// ===========================================================================
// Launch
// ===========================================================================
extern "C" void kernel_launch(void* const* d_in, const int* in_sizes, int n_in,
                              void* d_out, int out_size) {
    const float* u  = (const float*)d_in[0];
    const float* k0 = (const float*)d_in[1];
    const float* k1 = (const float*)d_in[2];
    const float* k2 = (const float*)d_in[3];
    const float* k3 = (const float*)d_in[4];
    const float* D  = (const float*)d_in[5];
    const float* Wm = (const float*)d_in[6];
    const float* b  = (const float*)d_in[7];
    float* out = (float*)d_out;

    build_filter_kernel<<<H, TAPS>>>(k0, k1, k2, k3);
    wprep_kernel<<<H * H / 256, 256>>>(Wm);

    conv_mma_kernel<<<BATCH * H, 128>>>(u, D);

    dim3 tgrid(L / 64, H / 64, BATCH);
    transpose_h_kernel<<<tgrid, 256>>>();

    static bool attr_set = false;
    if (!attr_set) {
        cudaFuncSetAttribute(gemm_mma_fp16,
                             cudaFuncAttributeMaxDynamicSharedMemorySize,
                             GEMM_SMEM_BYTES);
        attr_set = true;
    }
    dim3 ggrid(L / GBN, H / GBM, BATCH);
    gemm_mma_fp16<<<ggrid, 256, GEMM_SMEM_BYTES>>>(b, out);
}

// round 12
// speedup vs baseline: 1.8506x; 1.3761x over previous
#include <cuda_runtime.h>
#include <cuda_fp16.h>
#include <cstdint>
#include <math.h>

// Problem constants
#define BATCH 4
#define H 1024
#define L 8192
#define KD 64
#define NS 4
#define TAPS 512

// Scratch
__device__ float  g_filt[H * TAPS];                      // 2 MB
__device__ __half g_vh[(size_t)BATCH * H * L];           // 64 MB   v[b,h,l] fp16
__device__ __half g_wh[H * H];                           // 2 MB    W fp16

// ===========================================================================
// Helpers
// ===========================================================================
__device__ __forceinline__ void mma16n8k16h(float d[4], const uint32_t a[4],
                                            const uint32_t b0, const uint32_t b1,
                                            const float c[4]) {
    asm volatile(
        "mma.sync.aligned.m16n8k16.row.col.f32.f16.f16.f32 "
        "{%0,%1,%2,%3}, {%4,%5,%6,%7}, {%8,%9}, {%10,%11,%12,%13};"
        : "=f"(d[0]), "=f"(d[1]), "=f"(d[2]), "=f"(d[3])
        : "r"(a[0]), "r"(a[1]), "r"(a[2]), "r"(a[3]),
          "r"(b0), "r"(b1),
          "f"(c[0]), "f"(c[1]), "f"(c[2]), "f"(c[3]));
}

__device__ __forceinline__ void ldsm_x4(uint32_t& r0, uint32_t& r1,
                                        uint32_t& r2, uint32_t& r3, uint32_t addr) {
    asm volatile("ldmatrix.sync.aligned.m8n8.x4.shared.b16 {%0,%1,%2,%3}, [%4];"
                 : "=r"(r0), "=r"(r1), "=r"(r2), "=r"(r3) : "r"(addr));
}
__device__ __forceinline__ void ldsm_x4_t(uint32_t& r0, uint32_t& r1,
                                          uint32_t& r2, uint32_t& r3, uint32_t addr) {
    asm volatile("ldmatrix.sync.aligned.m8n8.x4.trans.shared.b16 {%0,%1,%2,%3}, [%4];"
                 : "=r"(r0), "=r"(r1), "=r"(r2), "=r"(r3) : "r"(addr));
}

__device__ __forceinline__ uint32_t smem_u32(const void* p) {
    uint32_t a;
    asm("{ .reg .u64 t; cvta.to.shared.u64 t, %1; cvt.u32.u64 %0, t; }" : "=r"(a) : "l"(p));
    return a;
}
__device__ __forceinline__ void cp_async16(uint32_t dst, const void* src) {
    asm volatile("cp.async.cg.shared.global [%0], [%1], 16;" :: "r"(dst), "l"(src));
}
__device__ __forceinline__ uint32_t packh2(float a, float b) {
    __half2 p = __floats2half2_rn(a, b);
    return *(uint32_t*)&p;
}

// ===========================================================================
// Kernel 1: build the multi-resolution filter, L2-normalized per head.
// ===========================================================================
__global__ void build_filter_kernel(const float* __restrict__ k0,
                                    const float* __restrict__ k1,
                                    const float* __restrict__ k2,
                                    const float* __restrict__ k3) {
    int h = blockIdx.x;
    int t = threadIdx.x;

    const float* ks[NS] = {k0, k1, k2, k3};
    float acc = 0.0f;
#pragma unroll
    for (int i = 0; i < NS; ++i) {
        int len = KD << i;
        if (t < len) {
            float scale = (float)(1 << i);
            float coord = ((float)t + 0.5f) / scale - 0.5f;
            coord = fminf(fmaxf(coord, 0.0f), (float)(KD - 1));
            int lo = (int)floorf(coord);
            int hi = min(lo + 1, KD - 1);
            float w = coord - (float)lo;
            const float* kp = ks[i] + h * KD;
            float v = kp[lo] * (1.0f - w) + kp[hi] * w;
            acc += v * (float)(1 << (NS - 1 - i));
        }
    }

    __shared__ float red[TAPS];
    red[t] = acc * acc;
    __syncthreads();
#pragma unroll
    for (int s = TAPS / 2; s > 0; s >>= 1) {
        if (t < s) red[t] += red[t + s];
        __syncthreads();
    }
    float inv_norm = rsqrtf(red[0]);
    g_filt[h * TAPS + t] = acc * inv_norm;
}

// ===========================================================================
// Kernel 1b: W -> fp16 copy
// ===========================================================================
__global__ void wprep_kernel(const float* __restrict__ Wm) {
    int i = blockIdx.x * 256 + threadIdx.x;
    g_wh[i] = __float2half_rn(Wm[i]);
}

// ===========================================================================
// Kernel 2: Toeplitz conv with fp16 m16n8k16: y = k (*) u + D*u, GeLU -> g_vh
//   u_s: fp16 pairs, rows of 64 elems (32 words) + 4 pad words (stride 36).
//   kp_s[j] = (filt[j], filt[j-1]) packed  (B's K axis runs backward).
// ===========================================================================
#define CUS 36    // u_s row stride in words

__global__ __launch_bounds__(128)
void conv_mma_fp16(const float* __restrict__ u, const float* __restrict__ D) {
    __shared__ uint32_t u_s[136 * CUS];
    __shared__ uint32_t kp_s[640];

    int bh = blockIdx.x;
    int h  = bh & (H - 1);
    int tid  = threadIdx.x;
    int lane = tid & 31;
    int wid  = tid >> 5;
    int gid = lane >> 2;
    int tig = lane & 3;

    int wm0 = (wid & 1) * 64;
    int wn0 = (wid >> 1) * 32;

    const float* up = u + (size_t)bh * L;

    // ---- filter pairs (with guards) ----
    for (int j = tid; j < 640; j += 128) {
        int t0 = j - 64, t1 = j - 65;
        float lo = (t0 >= 0 && t0 < TAPS) ? g_filt[h * TAPS + t0] : 0.0f;
        float hi = (t1 >= 0 && t1 < TAPS) ? g_filt[h * TAPS + t1] : 0.0f;
        kp_s[j] = packh2(lo, hi);
    }
    // ---- u guard rows (elements 0..511 -> rows 0..7) ----
    for (int w = tid; w < 256; w += 128)
        u_s[(w >> 5) * CUS + (w & 31)] = 0u;
    // ---- u data as fp16 pairs ----
    for (int j = tid; j < L / 4; j += 128) {
        float4 x = ((const float4*)up)[j];
        int e = 512 + j * 4;
        int row = e >> 6, w = (e & 63) >> 1;
        u_s[row * CUS + w]     = packh2(x.x, x.y);
        u_s[row * CUS + w + 1] = packh2(x.z, x.w);
    }
    __syncthreads();

    float acc[4][4][4];
#pragma unroll
    for (int s = 0; s < 4; ++s)
#pragma unroll
        for (int q = 0; q < 4; ++q)
#pragma unroll
            for (int e = 0; e < 4; ++e) acc[s][q][e] = 0.0f;

#pragma unroll 1
    for (int d = 0; d < 9; ++d) {
        int rbase = wm0 + gid + 8 - d;                    // u_s row for s=0
        int xbase = 64 + wn0 + gid - 2 * tig + 64 * d;    // kp index base
#pragma unroll
        for (int msi = 0; msi < 4; ++msi) {
            int msw = msi * 8;                            // word offset (ms/2)
            uint32_t a[4][4];
#pragma unroll
            for (int s = 0; s < 4; ++s) {
                int row = rbase + s * 16;
                a[s][0] = u_s[row * CUS + msw + tig];
                a[s][1] = u_s[(row + 8) * CUS + msw + tig];
                a[s][2] = u_s[row * CUS + msw + tig + 4];
                a[s][3] = u_s[(row + 8) * CUS + msw + tig + 4];
            }
            uint32_t b0[4], b1[4];
#pragma unroll
            for (int q = 0; q < 4; ++q) {
                int x = xbase + q * 8 - msi * 16;
                b0[q] = kp_s[x];
                b1[q] = kp_s[x - 8];
            }
#pragma unroll
            for (int s = 0; s < 4; ++s)
#pragma unroll
                for (int q = 0; q < 4; ++q)
                    mma16n8k16h(acc[s][q], a[s], b0[q], b1[q], acc[s][q]);
        }
    }

    // ---- epilogue: + D*u, exact GeLU, fp16 store ----
    float dv = D[h];
    __half* vp = g_vh + (size_t)bh * L;
#pragma unroll
    for (int s = 0; s < 4; ++s) {
#pragma unroll
        for (int q = 0; q < 4; ++q) {
            int n = wn0 + q * 8 + 2 * tig;
#pragma unroll
            for (int half = 0; half < 2; ++half) {
                int r = wm0 + s * 16 + gid + half * 8;
                uint32_t uw = u_s[(r + 8) * CUS + (n >> 1)];
                float2 uf = __half22float2(*(__half2*)&uw);
                float x0 = acc[s][q][half * 2 + 0] + dv * uf.x;
                float x1 = acc[s][q][half * 2 + 1] + dv * uf.y;
                float g0 = 0.5f * x0 * (1.0f + erff(x0 * 0.70710678118654752f));
                float g1 = 0.5f * x1 * (1.0f + erff(x1 * 0.70710678118654752f));
                *(__half2*)(vp + r * 64 + n) = __floats2half2_rn(g0, g1);
            }
        }
    }
}

// ===========================================================================
// Kernel 3: fp16 mma GEMM; B read DIRECTLY from g_vh[h][l] via ldmatrix.trans
//   out[b,o,l] = sum_f W[o,f] * v[b,f,l] + bias[o]
//   CTA tile 128(M=o) x 128(N=l) x 32(K=f); 8 warps (4M x 2N), warp 32x64.
//   A smem: [m][k] rows 64B + 16B pad (80B). B smem: [k][n] rows 256B + 16B (272B).
// ===========================================================================
#define GBM 128
#define GBN 128
#define GBK 32
#define ABS 80                               // A row stride bytes
#define BBS 272                              // B row stride bytes
#define A_STAGE_B (GBM * ABS)                // 10240
#define B_STAGE_B (GBK * BBS)                // 8704
#define STAGE_B (A_STAGE_B + B_STAGE_B)      // 18944
#define GSTG 4
#define GEMM_SMEM_BYTES (GSTG * STAGE_B)     // 75776
#define GNCHUNK (H / GBK)                    // 32

extern __shared__ uint32_t g_smem[];

__global__ __launch_bounds__(256, 2)
void gemm_mma_fp16(const float* __restrict__ bias, float* __restrict__ out) {
    int bz = blockIdx.z;
    int nb = blockIdx.x * GBN;
    int mb = blockIdx.y * GBM;
    const __half* vh = g_vh + (size_t)bz * H * L;

    int tid  = threadIdx.x;
    int lane = tid & 31;
    int wid  = tid >> 5;           // 0..7
    int wm0 = (wid & 3) * 32;      // warp M offset
    int wn0 = (wid >> 2) * 64;     // warp N offset
    int gid = lane >> 2;
    int tig = lane & 3;

    uint32_t sbase = smem_u32(g_smem);

    // cp.async fill mapping
    int rA = tid >> 2, sA = tid & 3;          // A: 64 rows/pass x 4 slots
    int rB = tid >> 4, sB = tid & 15;         // B: 16 rows/pass x 16 slots
    const __half* Ag = g_wh + (size_t)(mb + rA) * H + sA * 8;
    uint32_t a_dst = (uint32_t)(rA * ABS + sA * 16);
    uint32_t b_dst = (uint32_t)(rB * BBS + sB * 16);

    // ldmatrix lane offsets
    int l16 = lane & 15, lhi = lane >> 4;
    uint32_t a_off0 = (uint32_t)((wm0 + l16) * ABS + lhi * 16);
    uint32_t a_off1 = a_off0 + 16 * ABS;
    int l8 = lane & 7, lt = lane >> 3;        // tile id 0..3
    uint32_t b_lane = (uint32_t)(((lt & 1) * 8 + l8) * BBS + (lt >> 1) * 16);
    uint32_t b_off[4];
#pragma unroll
    for (int q = 0; q < 4; ++q)
        b_off[q] = b_lane + (uint32_t)((wn0 + q * 16) * 2);

#define ISSUE_CHUNK(c_) do {                                                  \
        int st_ = (c_) % GSTG;                                                \
        uint32_t sa_ = sbase + (uint32_t)(st_ * STAGE_B);                     \
        uint32_t sb_ = sa_ + (uint32_t)A_STAGE_B;                             \
        const __half* ag_ = Ag + (c_) * GBK;                                  \
        const __half* bg_ = vh + (size_t)((c_) * GBK + rB) * L + nb + sB * 8; \
        _Pragma("unroll")                                                     \
        for (int r_ = 0; r_ < 2; ++r_) {                                      \
            cp_async16(sa_ + a_dst + (uint32_t)(r_ * 64 * ABS),               \
                       ag_ + (size_t)(r_ * 64) * H);                          \
            cp_async16(sb_ + b_dst + (uint32_t)(r_ * 16 * BBS),               \
                       bg_ + (size_t)(r_ * 16) * L);                          \
        }                                                                     \
    } while (0)

#pragma unroll
    for (int c = 0; c < GSTG - 1; ++c) {
        ISSUE_CHUNK(c);
        asm volatile("cp.async.commit_group;" ::: "memory");
    }

    float acc[2][8][4];
#pragma unroll
    for (int s = 0; s < 2; ++s)
#pragma unroll
        for (int j = 0; j < 8; ++j)
#pragma unroll
            for (int e = 0; e < 4; ++e) acc[s][j][e] = 0.0f;

#pragma unroll 1
    for (int c = 0; c < GNCHUNK; ++c) {
        asm volatile("cp.async.wait_group %0;" :: "n"(GSTG - 2) : "memory");
        __syncthreads();

        if (c + GSTG - 1 < GNCHUNK) ISSUE_CHUNK(c + GSTG - 1);
        asm volatile("cp.async.commit_group;" ::: "memory");

        uint32_t sa = sbase + (uint32_t)((c % GSTG) * STAGE_B);
        uint32_t sb = sa + (uint32_t)A_STAGE_B;

#pragma unroll
        for (int ks = 0; ks < 2; ++ks) {       // two k16 steps per BK=32
            uint32_t a[2][4];
            ldsm_x4(a[0][0], a[0][1], a[0][2], a[0][3], sa + a_off0 + ks * 32);
            ldsm_x4(a[1][0], a[1][1], a[1][2], a[1][3], sa + a_off1 + ks * 32);
            uint32_t b0[8], b1[8];
#pragma unroll
            for (int q = 0; q < 4; ++q) {
                uint32_t t0, t1, t2, t3;
                ldsm_x4_t(t0, t1, t2, t3, sb + b_off[q] + (uint32_t)(ks * 16 * BBS));
                b0[q * 2]     = t0; b1[q * 2]     = t1;
                b0[q * 2 + 1] = t2; b1[q * 2 + 1] = t3;
            }
#pragma unroll
            for (int s = 0; s < 2; ++s)
#pragma unroll
                for (int j = 0; j < 8; ++j)
                    mma16n8k16h(acc[s][j], a[s], b0[j], b1[j], acc[s][j]);
        }
    }

    // ---- epilogue ----
#pragma unroll
    for (int s = 0; s < 2; ++s) {
        int r0 = mb + wm0 + s * 16 + gid;
        int r1 = r0 + 8;
        float bv0 = bias[r0];
        float bv1 = bias[r1];
        float* o0 = out + ((size_t)bz * H + r0) * L + nb + wn0 + tig * 2;
        float* o1 = out + ((size_t)bz * H + r1) * L + nb + wn0 + tig * 2;
#pragma unroll
        for (int j = 0; j < 8; ++j) {
            *(float2*)(o0 + j * 8) = make_float2(acc[s][j][0] + bv0, acc[s][j][1] + bv0);
            *(float2*)(o1 + j * 8) = make_float2(acc[s][j][2] + bv1, acc[s][j][3] + bv1);
        }
    }
}

// ===========================================================================
// Launch
// ===========================================================================
extern "C" void kernel_launch(void* const* d_in, const int* in_sizes, int n_in,
                              void* d_out, int out_size) {
    const float* u  = (const float*)d_in[0];
    const float* k0 = (const float*)d_in[1];
    const float* k1 = (const float*)d_in[2];
    const float* k2 = (const float*)d_in[3];
    const float* k3 = (const float*)d_in[4];
    const float* D  = (const float*)d_in[5];
    const float* Wm = (const float*)d_in[6];
    const float* b  = (const float*)d_in[7];
    float* out = (float*)d_out;

    build_filter_kernel<<<H, TAPS>>>(k0, k1, k2, k3);
    wprep_kernel<<<H * H / 256, 256>>>(Wm);

    conv_mma_fp16<<<BATCH * H, 128>>>(u, D);

    static bool attr_set = false;
    if (!attr_set) {
        cudaFuncSetAttribute(gemm_mma_fp16,
                             cudaFuncAttributeMaxDynamicSharedMemorySize,
                             GEMM_SMEM_BYTES);
        attr_set = true;
    }
    dim3 ggrid(L / GBN, H / GBM, BATCH);
    gemm_mma_fp16<<<ggrid, 256, GEMM_SMEM_BYTES>>>(b, out);
}